// round 1
// baseline (speedup 1.0000x reference)
#include <cuda_runtime.h>

// RoIAlign: input (N=2, C=256, H=200, W=200) f32, rois (K,5) f32 -> out (K,256,7,7) f32
// PH=PW=7, SR=2, SCALE=0.25

#define C_  256
#define H_  200
#define W_  200
#define PHW 7

__global__ __launch_bounds__(256) void roialign_kernel(
    const float* __restrict__ fm,
    const float* __restrict__ rois,
    float* __restrict__ out,
    int total)
{
    int idx = blockIdx.x * blockDim.x + threadIdx.x;
    if (idx >= total) return;

    int pw = idx % PHW;
    int t  = idx / PHW;
    int ph = t % PHW;
    t /= PHW;
    int c = t % C_;
    int k = t / C_;

    const float* r = rois + (size_t)k * 5;
    int   b  = (int)r[0];
    float x1 = r[1] * 0.25f;
    float y1 = r[2] * 0.25f;
    float x2 = r[3] * 0.25f;
    float y2 = r[4] * 0.25f;

    float roi_w = fmaxf(x2 - x1, 1.0f);
    float roi_h = fmaxf(y2 - y1, 1.0f);
    float bin_w = roi_w * (1.0f / 7.0f);
    float bin_h = roi_h * (1.0f / 7.0f);

    const float* base = fm + (((size_t)b * C_ + c) * (H_ * W_));

    float acc = 0.0f;

    #pragma unroll
    for (int sy = 0; sy < 2; sy++) {
        float oy = (float)ph + ((float)sy + 0.5f) * 0.5f;
        float y  = fmaf(oy, bin_h, y1);
        bool  vy = (y >= -1.0f) && (y <= (float)H_);
        float y0 = fmaxf(y, 0.0f);
        int   yl = min((int)floorf(y0), H_ - 1);
        int   yh = min(yl + 1, H_ - 1);
        float ly = y0 - (float)yl;
        float hy = 1.0f - ly;

        const float* rowl = base + yl * W_;
        const float* rowh = base + yh * W_;

        #pragma unroll
        for (int sx = 0; sx < 2; sx++) {
            float ox = (float)pw + ((float)sx + 0.5f) * 0.5f;
            float x  = fmaf(ox, bin_w, x1);
            bool  vx = (x >= -1.0f) && (x <= (float)W_);
            float x0 = fmaxf(x, 0.0f);
            int   xl = min((int)floorf(x0), W_ - 1);
            int   xh = min(xl + 1, W_ - 1);
            float lx = x0 - (float)xl;
            float hx = 1.0f - lx;

            float v00 = __ldg(rowl + xl);
            float v01 = __ldg(rowl + xh);
            float v10 = __ldg(rowh + xl);
            float v11 = __ldg(rowh + xh);

            float v = hy * (hx * v00 + lx * v01) + ly * (hx * v10 + lx * v11);
            if (vy && vx) acc += v;
        }
    }

    out[idx] = acc * 0.25f;
}

extern "C" void kernel_launch(void* const* d_in, const int* in_sizes, int n_in,
                              void* d_out, int out_size)
{
    const float* fm   = (const float*)d_in[0];
    const float* rois = (const float*)d_in[1];
    float*       out  = (float*)d_out;

    int K = in_sizes[1] / 5;
    int total = K * C_ * PHW * PHW;

    int threads = 256;
    int blocks = (total + threads - 1) / threads;
    roialign_kernel<<<blocks, threads>>>(fm, rois, out, total);
}

// round 3
// speedup vs baseline: 1.0852x; 1.0852x over previous
#include <cuda_runtime.h>

// RoIAlign: input (N=2, C=256, H=200, W=200) f32 NCHW, rois (K,5) f32 -> out (K,256,7,7) f32
// PH=PW=7, SR=2, SCALE=0.25
// Strategy: transpose input to NHWC once per launch, then gather with lanes
// across channels so every bilinear-corner load is a single 128B wavefront.

#define C_   256
#define H_   200
#define W_   200
#define HW_  (H_ * W_)
#define PHW  7

__device__ float g_nhwc[(size_t)2 * HW_ * C_];   // 81.92 MB scratch

// ---------------------------------------------------------------------------
// NCHW -> NHWC tiled transpose. Per batch: M[C][HW] -> T[HW][C].
// grid (HW/32=1250, C/32=8, N=2), block (32,8). Both sides coalesced.
// ---------------------------------------------------------------------------
__global__ __launch_bounds__(256) void transpose_kernel(const float* __restrict__ in)
{
    __shared__ float tile[32][33];
    int b  = blockIdx.z;
    int c0 = blockIdx.y * 32;
    int p0 = blockIdx.x * 32;
    int tx = threadIdx.x;
    int ty = threadIdx.y;

    const float* src = in + (size_t)b * C_ * HW_;
    #pragma unroll
    for (int j = 0; j < 32; j += 8)
        tile[ty + j][tx] = src[(size_t)(c0 + ty + j) * HW_ + p0 + tx];
    __syncthreads();

    float* dst = g_nhwc + (size_t)b * HW_ * C_;
    #pragma unroll
    for (int j = 0; j < 32; j += 8)
        dst[(size_t)(p0 + ty + j) * C_ + c0 + tx] = tile[tx][ty + j];
}

// ---------------------------------------------------------------------------
// Main kernel: grid (K, C/32), block 256 (8 warps).
// lane = channel within 32-group; warps stride over the 49 output bins.
// Per-roi corner index/weight tables built once in smem.
// Output staged in smem, written back fully coalesced.
// ---------------------------------------------------------------------------
__global__ __launch_bounds__(256) void roialign_nhwc_kernel(
    const float* __restrict__ rois,
    float* __restrict__ out)
{
    __shared__ int   s_yl[14], s_yh[14], s_xl[14], s_xh[14];
    __shared__ float s_ly[14], s_vy[14], s_lx[14], s_vx[14];
    __shared__ float s_out[32 * 49];

    int k    = blockIdx.x;
    int cg   = blockIdx.y;
    int tid  = threadIdx.x;
    int lane = tid & 31;
    int warp = tid >> 5;

    const float* r = rois + (size_t)k * 5;

    // Build per-roi sample tables (14 y-samples, 14 x-samples).
    if (tid < 28) {
        int dir = tid / 14;     // 0 = y, 1 = x
        int i   = tid % 14;
        float lo, span, Lf;
        int Lm1;
        if (dir == 0) {
            lo = r[2] * 0.25f;
            span = fmaxf(r[4] * 0.25f - lo, 1.0f);
            Lf = (float)H_;  Lm1 = H_ - 1;
        } else {
            lo = r[1] * 0.25f;
            span = fmaxf(r[3] * 0.25f - lo, 1.0f);
            Lf = (float)W_;  Lm1 = W_ - 1;
        }
        float binsz = span * (1.0f / 7.0f);
        int p = i >> 1, s = i & 1;
        float off = (float)p + ((float)s + 0.5f) * 0.5f;
        float t = fmaf(off, binsz, lo);
        float v = (t >= -1.0f && t <= Lf) ? 1.0f : 0.0f;
        float t0 = fmaxf(t, 0.0f);
        int lo_i = min((int)floorf(t0), Lm1);
        int hi_i = min(lo_i + 1, Lm1);
        float fr = t0 - (float)lo_i;
        if (dir == 0) { s_yl[i] = lo_i; s_yh[i] = hi_i; s_ly[i] = fr; s_vy[i] = v; }
        else          { s_xl[i] = lo_i; s_xh[i] = hi_i; s_lx[i] = fr; s_vx[i] = v; }
    }
    __syncthreads();

    int b = (int)r[0];
    const float* fb = g_nhwc + (size_t)b * HW_ * C_ + cg * 32 + lane;

    for (int s = warp; s < 49; s += 8) {
        int ph = s / PHW, pw = s % PHW;
        float acc = 0.0f;
        #pragma unroll
        for (int sy = 0; sy < 2; sy++) {
            int   iy = ph * 2 + sy;
            int   yl = s_yl[iy], yh = s_yh[iy];
            float ly = s_ly[iy];
            float hy = 1.0f - ly;
            float vy = s_vy[iy];
            #pragma unroll
            for (int sx = 0; sx < 2; sx++) {
                int   ix = pw * 2 + sx;
                int   xl = s_xl[ix], xh = s_xh[ix];
                float lx = s_lx[ix];
                float hx = 1.0f - lx;
                float m  = vy * s_vx[ix];

                float v00 = __ldg(fb + (size_t)(yl * W_ + xl) * C_);
                float v01 = __ldg(fb + (size_t)(yl * W_ + xh) * C_);
                float v10 = __ldg(fb + (size_t)(yh * W_ + xl) * C_);
                float v11 = __ldg(fb + (size_t)(yh * W_ + xh) * C_);

                float val = hy * (hx * v00 + lx * v01) + ly * (hx * v10 + lx * v11);
                acc = fmaf(m, val, acc);
            }
        }
        s_out[lane * 49 + s] = acc * 0.25f;
    }
    __syncthreads();

    // Coalesced writeback: out[k][cg*32 .. cg*32+31][0..48] is one contiguous
    // 1568-float chunk in (k,c,ph,pw) order, and s_out is laid out identically.
    float* ob = out + ((size_t)k * C_ + cg * 32) * 49;
    #pragma unroll
    for (int t = tid; t < 32 * 49; t += 256)
        ob[t] = s_out[t];
}

extern "C" void kernel_launch(void* const* d_in, const int* in_sizes, int n_in,
                              void* d_out, int out_size)
{
    const float* fm   = (const float*)d_in[0];
    const float* rois = (const float*)d_in[1];
    float*       out  = (float*)d_out;

    int K = in_sizes[1] / 5;

    dim3 tgrid(HW_ / 32, C_ / 32, 2);
    dim3 tblk(32, 8);
    transpose_kernel<<<tgrid, tblk>>>(fm);

    dim3 mgrid(K, C_ / 32);
    roialign_nhwc_kernel<<<mgrid, 256>>>(rois, out);
}

// round 4
// speedup vs baseline: 1.2773x; 1.1770x over previous
#include <cuda_runtime.h>
#include <cuda_fp16.h>

// RoIAlign: input (N=2, C=256, H=200, W=200) f32 NCHW, rois (K,5) f32 -> out (K,256,7,7) f32
// PH=PW=7, SR=2, SCALE=0.25
// Strategy: one-time NCHW->NHWC transpose into fp16 scratch; main kernel gathers
// with lanes across channels (8 halfs per lane = 512B per warp-load), all
// per-sample offsets/weights precomputed into smem, fp32 accumulation.

#define C_   256
#define H_   200
#define W_   200
#define HW_  (H_ * W_)
#define PHW  7

__device__ __half g_nhwc[(size_t)2 * HW_ * C_];   // 40.96 MB scratch (L2-resident)

// ---------------------------------------------------------------------------
// NCHW f32 -> NHWC fp16 tiled transpose. grid (HW/32, C/64, N), block (32,8).
// ---------------------------------------------------------------------------
__global__ __launch_bounds__(256) void transpose_kernel(const float* __restrict__ in)
{
    __shared__ float tile[64][33];
    int b  = blockIdx.z;
    int c0 = blockIdx.y * 64;
    int p0 = blockIdx.x * 32;
    int tx = threadIdx.x;
    int ty = threadIdx.y;

    const float* src = in + (size_t)b * C_ * HW_;
    #pragma unroll
    for (int cy = ty; cy < 64; cy += 8)
        tile[cy][tx] = src[(size_t)(c0 + cy) * HW_ + p0 + tx];
    __syncthreads();

    __half* dst = g_nhwc + (size_t)b * HW_ * C_;
    #pragma unroll
    for (int row = ty; row < 32; row += 8) {
        __half2 v = __floats2half2_rn(tile[2 * tx][row], tile[2 * tx + 1][row]);
        *(__half2*)(dst + (size_t)(p0 + row) * C_ + c0 + 2 * tx) = v;
    }
}

// ---------------------------------------------------------------------------
// Main kernel: grid (K), block 256 (8 warps). One block = one roi, all 256 ch.
// lane covers 8 channels (uint4 = 8 halfs). Warps stride over the 49 bins.
// smem: per-sample corner offsets + pre-folded weights; output staging.
// ---------------------------------------------------------------------------
__global__ __launch_bounds__(256) void roialign_kernel(
    const float* __restrict__ rois,
    float* __restrict__ out)
{
    __shared__ int   s_off[196][4];
    __shared__ float s_w[196][4];
    __shared__ float s_out[C_ * 49];

    int k    = blockIdx.x;
    int tid  = threadIdx.x;
    int lane = tid & 31;
    int warp = tid >> 5;

    const float* r = rois + (size_t)k * 5;

    if (tid < 196) {
        int bin = tid >> 2, q = tid & 3;
        int ph = bin / 7, pw = bin % 7;
        int sy = q >> 1, sx = q & 1;

        float y1 = r[2] * 0.25f;
        float bh = fmaxf(r[4] * 0.25f - y1, 1.0f) * (1.0f / 7.0f);
        float y  = fmaf((float)ph + ((float)sy + 0.5f) * 0.5f, bh, y1);
        bool  vy = (y >= -1.0f) && (y <= (float)H_);
        float y0 = fmaxf(y, 0.0f);
        int   yl = min((int)floorf(y0), H_ - 1);
        int   yh = min(yl + 1, H_ - 1);
        float ly = y0 - (float)yl;
        float hy = 1.0f - ly;

        float x1 = r[1] * 0.25f;
        float bw = fmaxf(r[3] * 0.25f - x1, 1.0f) * (1.0f / 7.0f);
        float x  = fmaf((float)pw + ((float)sx + 0.5f) * 0.5f, bw, x1);
        bool  vx = (x >= -1.0f) && (x <= (float)W_);
        float x0 = fmaxf(x, 0.0f);
        int   xl = min((int)floorf(x0), W_ - 1);
        int   xh = min(xl + 1, W_ - 1);
        float lx = x0 - (float)xl;
        float hx = 1.0f - lx;

        float m = (vy && vx) ? 0.25f : 0.0f;

        s_off[tid][0] = (yl * W_ + xl) * C_;
        s_off[tid][1] = (yl * W_ + xh) * C_;
        s_off[tid][2] = (yh * W_ + xl) * C_;
        s_off[tid][3] = (yh * W_ + xh) * C_;
        s_w[tid][0] = m * hy * hx;
        s_w[tid][1] = m * hy * lx;
        s_w[tid][2] = m * ly * hx;
        s_w[tid][3] = m * ly * lx;
    }
    __syncthreads();

    int b = (int)r[0];
    const __half* fb = g_nhwc + (size_t)b * HW_ * C_ + lane * 8;

    for (int s = warp; s < 49; s += 8) {
        float acc[8] = {0.f, 0.f, 0.f, 0.f, 0.f, 0.f, 0.f, 0.f};

        #pragma unroll
        for (int q = 0; q < 4; q++) {
            int smp = s * 4 + q;
            int4   off = *(const int4*)s_off[smp];
            float4 w   = *(const float4*)s_w[smp];

            uint4 p0 = __ldg((const uint4*)(fb + off.x));
            uint4 p1 = __ldg((const uint4*)(fb + off.y));
            uint4 p2 = __ldg((const uint4*)(fb + off.z));
            uint4 p3 = __ldg((const uint4*)(fb + off.w));

            const __half2* h0 = (const __half2*)&p0;
            const __half2* h1 = (const __half2*)&p1;
            const __half2* h2 = (const __half2*)&p2;
            const __half2* h3 = (const __half2*)&p3;

            #pragma unroll
            for (int j = 0; j < 4; j++) {
                float2 f0 = __half22float2(h0[j]);
                float2 f1 = __half22float2(h1[j]);
                float2 f2 = __half22float2(h2[j]);
                float2 f3 = __half22float2(h3[j]);
                acc[2*j]   = fmaf(w.x, f0.x, acc[2*j]);
                acc[2*j+1] = fmaf(w.x, f0.y, acc[2*j+1]);
                acc[2*j]   = fmaf(w.y, f1.x, acc[2*j]);
                acc[2*j+1] = fmaf(w.y, f1.y, acc[2*j+1]);
                acc[2*j]   = fmaf(w.z, f2.x, acc[2*j]);
                acc[2*j+1] = fmaf(w.z, f2.y, acc[2*j+1]);
                acc[2*j]   = fmaf(w.w, f3.x, acc[2*j]);
                acc[2*j+1] = fmaf(w.w, f3.y, acc[2*j+1]);
            }
        }

        #pragma unroll
        for (int j = 0; j < 8; j++)
            s_out[(lane * 8 + j) * 49 + s] = acc[j];
    }
    __syncthreads();

    // out[k][0..255][7][7] is one contiguous 12544-float chunk matching s_out layout.
    float* ob = out + (size_t)k * C_ * 49;
    for (int t = tid; t < C_ * 49; t += 256)
        ob[t] = s_out[t];
}

extern "C" void kernel_launch(void* const* d_in, const int* in_sizes, int n_in,
                              void* d_out, int out_size)
{
    const float* fm   = (const float*)d_in[0];
    const float* rois = (const float*)d_in[1];
    float*       out  = (float*)d_out;

    int K = in_sizes[1] / 5;

    dim3 tgrid(HW_ / 32, C_ / 64, 2);
    dim3 tblk(32, 8);
    transpose_kernel<<<tgrid, tblk>>>(fm);

    roialign_kernel<<<K, 256>>>(rois, out);
}

// round 10
// speedup vs baseline: 1.7701x; 1.3858x over previous
#include <cuda_runtime.h>
#include <cuda_fp16.h>

// RoIAlign: input (N=2, C=256, H=200, W=200) f32 NCHW, rois (K,5) f32 -> out (K,256,7,7) f32
// PH=PW=7, SR=2, SCALE=0.25

#define C_   256
#define H_   200
#define W_   200
#define HW_  (H_ * W_)
#define PHW  7

__device__ __half g_nhwc[(size_t)2 * HW_ * C_];   // 40.96 MB scratch (L2-resident)

// ---------------------------------------------------------------------------
// NCHW f32 -> NHWC fp16 transpose, conflict-free smem via half2 channel pairs.
// Tile: 128 channels (64 pairs) x 32 positions. grid (HW/32, C/128, N), block 256.
// ---------------------------------------------------------------------------
__global__ __launch_bounds__(256) void transpose_kernel(const float* __restrict__ in)
{
    __shared__ __half2 tile[64][33];   // [channel-pair][position]
    int b  = blockIdx.z;
    int c0 = blockIdx.y * 128;
    int p0 = blockIdx.x * 32;
    int tid = threadIdx.x;
    int tx = tid & 31;        // position within tile
    int ty = tid >> 5;        // 0..7

    const float* src = in + (size_t)b * C_ * HW_ + (size_t)c0 * HW_ + p0;
    #pragma unroll
    for (int cp = ty; cp < 64; cp += 8) {
        float a = src[(size_t)(2 * cp)     * HW_ + tx];
        float c = src[(size_t)(2 * cp + 1) * HW_ + tx];
        tile[cp][tx] = __floats2half2_rn(a, c);
    }
    __syncthreads();

    // Write phase: cover ALL 64 pairs x 32 positions with 256 threads.
    // cp = tid & 63 (lanes span 32 consecutive pairs -> 128B coalesced stores;
    // smem bank = cp + row mod 32 -> conflict-free).
    __half2* dst = (__half2*)(g_nhwc + (size_t)b * HW_ * C_ + c0);
    int cp_ = tid & 63;
    int rsub = tid >> 6;      // 0..3
    #pragma unroll
    for (int rb = 0; rb < 32; rb += 4) {
        int row = rb + rsub;
        dst[(size_t)(p0 + row) * (C_ / 2) + cp_] = tile[cp_][row];
    }
}

// ---------------------------------------------------------------------------
// Main kernel: grid (K, 2), block 256 (8 warps). One block = one roi x 128 ch.
// lane covers 4 channels (uint2 = 4 halfs); warps stride over the 49 bins.
// Per-sample corner offsets + pre-folded weights in smem; staged writeback.
// ---------------------------------------------------------------------------
__global__ __launch_bounds__(256) void roialign_kernel(
    const float* __restrict__ rois,
    float* __restrict__ out)
{
    __shared__ int   s_off[196][4];
    __shared__ float s_w[196][4];
    __shared__ float s_out[128 * 49];

    int k    = blockIdx.x;
    int half = blockIdx.y;           // which 128-channel slab
    int tid  = threadIdx.x;
    int lane = tid & 31;
    int warp = tid >> 5;

    const float* r = rois + (size_t)k * 5;

    if (tid < 196) {
        int bin = tid >> 2, q = tid & 3;
        int ph = bin / 7, pw = bin % 7;
        int sy = q >> 1, sx = q & 1;

        float y1 = r[2] * 0.25f;
        float bh = fmaxf(r[4] * 0.25f - y1, 1.0f) * (1.0f / 7.0f);
        float y  = fmaf((float)ph + ((float)sy + 0.5f) * 0.5f, bh, y1);
        bool  vy = (y >= -1.0f) && (y <= (float)H_);
        float y0 = fmaxf(y, 0.0f);
        int   yl = min((int)floorf(y0), H_ - 1);
        int   yh = min(yl + 1, H_ - 1);
        float ly = y0 - (float)yl;
        float hy = 1.0f - ly;

        float x1 = r[1] * 0.25f;
        float bw = fmaxf(r[3] * 0.25f - x1, 1.0f) * (1.0f / 7.0f);
        float x  = fmaf((float)pw + ((float)sx + 0.5f) * 0.5f, bw, x1);
        bool  vx = (x >= -1.0f) && (x <= (float)W_);
        float x0 = fmaxf(x, 0.0f);
        int   xl = min((int)floorf(x0), W_ - 1);
        int   xh = min(xl + 1, W_ - 1);
        float lx = x0 - (float)xl;
        float hx = 1.0f - lx;

        float m = (vy && vx) ? 0.25f : 0.0f;

        s_off[tid][0] = (yl * W_ + xl) * C_;
        s_off[tid][1] = (yl * W_ + xh) * C_;
        s_off[tid][2] = (yh * W_ + xl) * C_;
        s_off[tid][3] = (yh * W_ + xh) * C_;
        s_w[tid][0] = m * hy * hx;
        s_w[tid][1] = m * hy * lx;
        s_w[tid][2] = m * ly * hx;
        s_w[tid][3] = m * ly * lx;
    }
    __syncthreads();

    int b = (int)r[0];
    const __half* fb = g_nhwc + (size_t)b * HW_ * C_ + half * 128 + lane * 4;

    for (int s = warp; s < 49; s += 8) {
        float acc0 = 0.f, acc1 = 0.f, acc2 = 0.f, acc3 = 0.f;

        #pragma unroll
        for (int q = 0; q < 4; q++) {
            int smp = s * 4 + q;
            int4   off = *(const int4*)s_off[smp];
            float4 w   = *(const float4*)s_w[smp];

            uint2 p0 = __ldg((const uint2*)(fb + off.x));
            uint2 p1 = __ldg((const uint2*)(fb + off.y));
            uint2 p2 = __ldg((const uint2*)(fb + off.z));
            uint2 p3 = __ldg((const uint2*)(fb + off.w));

            float2 a0 = __half22float2(*(const __half2*)&p0.x);
            float2 b0 = __half22float2(*(const __half2*)&p0.y);
            float2 a1 = __half22float2(*(const __half2*)&p1.x);
            float2 b1 = __half22float2(*(const __half2*)&p1.y);
            float2 a2 = __half22float2(*(const __half2*)&p2.x);
            float2 b2 = __half22float2(*(const __half2*)&p2.y);
            float2 a3 = __half22float2(*(const __half2*)&p3.x);
            float2 b3 = __half22float2(*(const __half2*)&p3.y);

            acc0 = fmaf(w.x, a0.x, acc0); acc1 = fmaf(w.x, a0.y, acc1);
            acc2 = fmaf(w.x, b0.x, acc2); acc3 = fmaf(w.x, b0.y, acc3);
            acc0 = fmaf(w.y, a1.x, acc0); acc1 = fmaf(w.y, a1.y, acc1);
            acc2 = fmaf(w.y, b1.x, acc2); acc3 = fmaf(w.y, b1.y, acc3);
            acc0 = fmaf(w.z, a2.x, acc0); acc1 = fmaf(w.z, a2.y, acc1);
            acc2 = fmaf(w.z, b2.x, acc2); acc3 = fmaf(w.z, b2.y, acc3);
            acc0 = fmaf(w.w, a3.x, acc0); acc1 = fmaf(w.w, a3.y, acc1);
            acc2 = fmaf(w.w, b3.x, acc2); acc3 = fmaf(w.w, b3.y, acc3);
        }

        int cb = lane * 4;
        s_out[(cb + 0) * 49 + s] = acc0;
        s_out[(cb + 1) * 49 + s] = acc1;
        s_out[(cb + 2) * 49 + s] = acc2;
        s_out[(cb + 3) * 49 + s] = acc3;
    }
    __syncthreads();

    // out[k][half*128 .. half*128+127][7][7] is one contiguous 6272-float chunk.
    float* ob = out + ((size_t)k * C_ + half * 128) * 49;
    for (int t = tid; t < 128 * 49; t += 256)
        ob[t] = s_out[t];
}

extern "C" void kernel_launch(void* const* d_in, const int* in_sizes, int n_in,
                              void* d_out, int out_size)
{
    const float* fm   = (const float*)d_in[0];
    const float* rois = (const float*)d_in[1];
    float*       out  = (float*)d_out;

    int K = in_sizes[1] / 5;

    dim3 tgrid(HW_ / 32, C_ / 128, 2);
    transpose_kernel<<<tgrid, 256>>>(fm);

    dim3 mgrid(K, 2);
    roialign_kernel<<<mgrid, 256>>>(rois, out);
}